// round 1
// baseline (speedup 1.0000x reference)
#include <cuda_runtime.h>

#define B_   256
#define T_   1024
#define NUM_ 126
#define L_   128

__device__ int d_perm[B_];

// Rank-sort sequences by length (descending), deterministic, O(n^2) with n=256.
__global__ void crf_sort_kernel(const int* __restrict__ lens){
    __shared__ int sl[B_];
    int i = threadIdx.x;
    sl[i] = lens[i];
    __syncthreads();
    int v = sl[i];
    int r = 0;
    #pragma unroll 8
    for (int j = 0; j < B_; j++){
        int w = sl[j];
        r += (int)((w > v) | ((w == v) & (j < i)));
    }
    d_perm[r] = i;
}

__device__ __forceinline__ void ffma2(unsigned long long &d, unsigned long long a, unsigned long long b){
    asm volatile("fma.rn.f32x2 %0, %1, %2, %0;" : "+l"(d) : "l"(a), "l"(b));
}
__device__ __forceinline__ unsigned long long fadd2(unsigned long long a, unsigned long long b){
    unsigned long long d;
    asm volatile("add.rn.f32x2 %0, %1, %2;" : "=l"(d) : "l"(a), "l"(b));
    return d;
}

// s[j] = sum_i E[j,i] * p[i], E held as 64 packed f32x2 registers, p broadcast from smem.
__device__ __forceinline__ float dot128(const float* __restrict__ p, const unsigned long long* __restrict__ E){
    const ulonglong2* pd = (const ulonglong2*)p;
    unsigned long long a0 = 0ull, a1 = 0ull, a2 = 0ull, a3 = 0ull;
    #pragma unroll
    for (int i = 0; i < 32; i += 2){
        ulonglong2 q0 = pd[i];
        ulonglong2 q1 = pd[i + 1];
        ffma2(a0, E[2*i + 0], q0.x);
        ffma2(a1, E[2*i + 1], q0.y);
        ffma2(a2, E[2*i + 2], q1.x);
        ffma2(a3, E[2*i + 3], q1.y);
    }
    unsigned long long s2 = fadd2(fadd2(a0, a1), fadd2(a2, a3));
    return __uint_as_float((unsigned)(s2 & 0xffffffffull)) +
           __uint_as_float((unsigned)(s2 >> 32));
}

#define GBAR(id) asm volatile("bar.sync %0, 128;" :: "r"(id) : "memory")

__global__ void __launch_bounds__(256, 1)
crf_main_kernel(const float* __restrict__ logits,
                const int*   __restrict__ labels,
                const int*   __restrict__ lens,
                const float* __restrict__ trans,
                float*       __restrict__ out)
{
    __shared__ __align__(16) float pbuf_all[2][2][L_];
    __shared__ float red_all[2][8];

    const int tid   = threadIdx.x;
    const int grp   = tid >> 7;        // 0 or 1: two independent sequence groups per CTA
    const int jt    = tid & 127;       // label index owned by this thread
    const int lane  = jt & 31;
    const int wrp   = jt >> 5;
    const int barid = 1 + grp;

    // Pair longest with shortest: group0 -> rank blockIdx.x, group1 -> rank 255-blockIdx.x
    const int rank = (grp == 0) ? (int)blockIdx.x : (B_ - 1 - (int)blockIdx.x);
    const int seq  = d_perm[rank];
    const int len  = lens[seq];

    float (*pb)[L_] = pbuf_all[grp];
    float* red      = red_all[grp];

    // ---- E row (exp of transition row jt) in registers: 64 packed f32x2 ----
    unsigned long long Ereg[64];
    {
        const float* trow = trans + jt * L_;
        #pragma unroll
        for (int m = 0; m < 64; m++){
            float e0 = expf(trow[2*m]);
            float e1 = expf(trow[2*m + 1]);
            Ereg[m] = (unsigned long long)__float_as_uint(e0)
                    | ((unsigned long long)__float_as_uint(e1) << 32);
        }
    }

    const float* lgp = logits + (size_t)seq * T_ * NUM_;

    // ---- gold score partial (threads stride over time) ----
    float gpart = 0.f;
    {
        const int* lab = labels + seq * T_;
        for (int t = jt; t < len; t += 128){
            int l1 = lab[t];
            gpart += lgp[(size_t)t * NUM_ + l1];
            int l0 = (t == 0) ? (L_ - 2) : lab[t - 1];
            gpart += trans[l1 * L_ + l0];
        }
        if (jt == 0) gpart += trans[(L_ - 1) * L_ + lab[len - 1]];
    }

    // ---- init p0: start state = 1, everything else 0 (e^-100 terms negligible) ----
    pb[0][jt] = (jt == (L_ - 2)) ? 1.f : 0.f;
    GBAR(barid);

    float lgbuf[4];
    #pragma unroll
    for (int k = 0; k < 4; k++)
        lgbuf[k] = (jt < NUM_) ? __ldg(lgp + (size_t)k * NUM_ + jt) : 0.f;

    float c    = 0.f;   // accumulated log-scale
    float pend = 1.f;   // pending 1/m from the last renormalization
    int   t0   = 0;

    // ---- main scan: blocks of 4 steps, renorm every 4th step, prefetch 4 ahead ----
    while (t0 + 4 <= len){
        float nbuf[4];
        #pragma unroll
        for (int k = 0; k < 4; k++){
            int tp = t0 + 4 + k;
            nbuf[k] = (jt < NUM_ && tp < T_) ? __ldg(lgp + (size_t)tp * NUM_ + jt) : 0.f;
        }
        #pragma unroll
        for (int k = 0; k < 4; k++){
            float s = dot128(pb[k & 1], Ereg);
            float u = (jt < NUM_) ? __expf(lgbuf[k]) : 0.f;  // padded labels -> exp(-1000)=0
            float v = s * u;
            if (k == 0) v *= pend;
            if (k == 3){
                float mw = v;
                #pragma unroll
                for (int o = 16; o; o >>= 1)
                    mw = fmaxf(mw, __shfl_xor_sync(0xffffffffu, mw, o));
                if (lane == 0) red[wrp] = mw;
            }
            pb[(k & 1) ^ 1][jt] = v;
            GBAR(barid);
            if (k == 3){
                float m = fmaxf(fmaxf(red[0], red[1]), fmaxf(red[2], red[3]));
                pend = __fdividef(1.f, m);
                c += __logf(m);
            }
        }
        #pragma unroll
        for (int k = 0; k < 4; k++) lgbuf[k] = nbuf[k];
        t0 += 4;
    }

    // ---- remainder (0..3 steps), renorm every step ----
    int rem = len - t0;
    #pragma unroll
    for (int k = 0; k < 3; k++){
        if (k < rem){
            float s = dot128(pb[k & 1], Ereg);
            float u = (jt < NUM_) ? __expf(lgbuf[k]) : 0.f;
            float v = s * u * pend;
            float mw = v;
            #pragma unroll
            for (int o = 16; o; o >>= 1)
                mw = fmaxf(mw, __shfl_xor_sync(0xffffffffu, mw, o));
            if (lane == 0) red[wrp] = mw;
            pb[(k & 1) ^ 1][jt] = v;
            GBAR(barid);
            float m = fmaxf(fmaxf(red[0], red[1]), fmaxf(red[2], red[3]));
            pend = __fdividef(1.f, m);
            c += __logf(m);
        }
    }

    // ---- epilogue: norm = c + log(pend * sum_i p[i]*exp(Tr[end,i])) ; out = gold - norm ----
    GBAR(barid);  // protect red[] reads of the last renorm from epilogue writes
    const float* pcur = pb[rem & 1];
    float term = pcur[jt] * __expf(trans[(L_ - 1) * L_ + jt]);
    #pragma unroll
    for (int o = 16; o; o >>= 1){
        term  += __shfl_xor_sync(0xffffffffu, term,  o);
        gpart += __shfl_xor_sync(0xffffffffu, gpart, o);
    }
    if (lane == 0){ red[wrp] = term; red[4 + wrp] = gpart; }
    GBAR(barid);
    if (jt == 0){
        float S = red[0] + red[1] + red[2] + red[3];
        float G = red[4] + red[5] + red[6] + red[7];
        out[seq] = G - (c + __logf(S * pend));
    }
}

extern "C" void kernel_launch(void* const* d_in, const int* in_sizes, int n_in,
                              void* d_out, int out_size)
{
    (void)in_sizes; (void)n_in; (void)out_size;
    const float* logits = (const float*)d_in[0];
    const int*   labels = (const int*)d_in[1];
    const int*   lens   = (const int*)d_in[2];
    const float* trans  = (const float*)d_in[3];
    float*       out    = (float*)d_out;

    crf_sort_kernel<<<1, B_>>>(lens);
    crf_main_kernel<<<B_ / 2, 256>>>(logits, labels, lens, trans, out);
}